// round 10
// baseline (speedup 1.0000x reference)
#include <cuda_runtime.h>
#include <cuda_fp16.h>
#include <stdint.h>

#define NN 8192
#define DD 512
#define LOGIT_SCALE 2.659f
#define FSCALE 32.0f
#define SC (LOGIT_SCALE / (FSCALE * FSCALE))
#define BM 256
#define BN 128
#define BK 64                              // fp8 elems per k-chunk (64 B/row)
#define NITER (DD / BK)                    // 8
#define NSTAGE 3

// dynamic SMEM layout (bytes)
#define SM_A(s)   ((s) * 16384)            // 3 x 16KB  (256 rows x 64B)
#define SM_B(s)   (49152 + (s) * 8192)     // 3 x 8KB   (128 rows x 64B)
#define SM_LABI   73728                    // 256 ints
#define SM_LABJ   74752                    // 128 ints
#define SM_ROWZ   75264                    // 256 f
#define SM_ROWW   76288
#define SM_COLZ   77312                    // 128 f
#define SM_COLW   77824
#define SM_TOTAL  78336

// ---- scratch (__device__ globals; no allocations allowed) ----
__device__ uint8_t g_imgQ[NN * DD];        // e4m3, normalized features x FSCALE
__device__ uint8_t g_txtQ[NN * DD];
__device__ float g_stats[4 * NN];          // [Zimg | Ztxt | Wimg | Wtxt]
__device__ int   g_cnt[100];
__device__ int   g_lab64;

// =============== helpers ===============
__device__ __forceinline__ uint32_t smem_u32(const void* p) {
    uint32_t a;
    asm("{ .reg .u64 t; cvta.to.shared.u64 t, %1; cvt.u32.u64 %0, t; }" : "=r"(a) : "l"(p));
    return a;
}
__device__ __forceinline__ void cp_async16(uint32_t s, const void* g) {
    uint64_t gg;
    asm("cvta.to.global.u64 %0, %1;" : "=l"(gg) : "l"(g));
    asm volatile("cp.async.cg.shared.global [%0], [%1], 16;" :: "r"(s), "l"(gg) : "memory");
}
#define CP_COMMIT() asm volatile("cp.async.commit_group;" ::: "memory")
#define CP_WAIT(n)  asm volatile("cp.async.wait_group %0;" :: "n"(n) : "memory")

__device__ __forceinline__ void ldsm_x4(uint32_t* r, uint32_t addr) {
    asm volatile("ldmatrix.sync.aligned.m8n8.x4.shared.b16 {%0,%1,%2,%3}, [%4];"
                 : "=r"(r[0]), "=r"(r[1]), "=r"(r[2]), "=r"(r[3]) : "r"(addr));
}
// fp8 e4m3 MMA, m16n8k32, fp16 accumulate
__device__ __forceinline__ void mma_fp8_h(uint32_t* d, const uint32_t* a, uint32_t b0, uint32_t b1) {
    asm volatile("mma.sync.aligned.m16n8k32.row.col.f16.e4m3.e4m3.f16 "
                 "{%0,%1}, {%2,%3,%4,%5}, {%6,%7}, {%0,%1};"
                 : "+r"(d[0]), "+r"(d[1])
                 : "r"(a[0]), "r"(a[1]), "r"(a[2]), "r"(a[3]), "r"(b0), "r"(b1));
}
__device__ __forceinline__ uint16_t pack_e4m3x2(float lo, float hi) {
    uint16_t r;
    asm("cvt.rn.satfinite.e4m3x2.f32 %0, %2, %1;" : "=h"(r) : "f"(lo), "f"(hi));
    return r;
}

// swizzled byte offset inside a [rows x 64B] stage (4 x 16B chunks per row)
__device__ __forceinline__ uint32_t sw_off(int row, int ch) {
    return (uint32_t)(row * 4 + (ch ^ ((row >> 1) & 3))) * 16u;
}

__device__ __forceinline__ int get_label(const int* __restrict__ labels, int i) {
    return g_lab64 ? labels[2 * i] : labels[i];
}

// ---------------- detect labels dtype + zero g_cnt + zero out ----------------
__global__ void detect_labels_kernel(const int* __restrict__ labels, float* __restrict__ out) {
    __shared__ int bad;
    const int t = threadIdx.x;
    if (t == 0) { bad = 0; out[0] = 0.0f; }
    if (t < 100) g_cnt[t] = 0;
    __syncthreads();
    int mybad = 0;
    for (int i = t; i < NN / 2; i += blockDim.x) {
        int lo = labels[2 * i];
        int hi = labels[2 * i + 1];
        if (hi != (lo < 0 ? -1 : 0)) mybad = 1;
    }
    if (mybad) bad = 1;
    __syncthreads();
    if (t == 0) g_lab64 = (bad == 0) ? 1 : 0;
}

// ---------------- normalize + fp32 -> e4m3(xFSCALE) + zero stats ----------------
__global__ void prep_kernel(const float* __restrict__ txt, const float* __restrict__ img) {
    const int row = blockIdx.x;
    const int t = threadIdx.x;
    const float* __restrict__ src = blockIdx.y ? txt : img;
    uint8_t* __restrict__ dst = blockIdx.y ? g_txtQ : g_imgQ;

    if (blockIdx.y == 0 && t < 4) g_stats[row * 4 + t] = 0.0f;

    float4 v = reinterpret_cast<const float4*>(src)[row * (DD / 4) + t];
    float ss = v.x * v.x + v.y * v.y + v.z * v.z + v.w * v.w;
#pragma unroll
    for (int m = 16; m; m >>= 1) ss += __shfl_xor_sync(0xffffffffu, ss, m);
    __shared__ float sm[4];
    if ((t & 31) == 0) sm[t >> 5] = ss;
    __syncthreads();
    float tot = sm[0] + sm[1] + sm[2] + sm[3];
    float inv = FSCALE / fmaxf(sqrtf(tot), 1e-12f);
    uint16_t lo = pack_e4m3x2(v.x * inv, v.y * inv);
    uint16_t hi = pack_e4m3x2(v.z * inv, v.w * inv);
    reinterpret_cast<uint32_t*>(dst)[row * (DD / 4) + t] = (uint32_t)lo | ((uint32_t)hi << 16);
}

// ---------------- label histogram (parallel; independent of gemm) ----------------
__global__ void hist_kernel(const int* __restrict__ labels) {
    int i = blockIdx.x * blockDim.x + threadIdx.x;
    if (i < NN) {
        int l = get_label(labels, i);
        if (l >= 0) atomicAdd(&g_cnt[l], 1);
    }
}

// ---------------- FP8 QMMA GEMM (warp tile 64x64) + fused statistics ----------------
// grid (NN/BN=64, NN/BM=32), 256 threads (8 warps = 4M x 2N).
__global__ __launch_bounds__(256, 2) void gemm_mma_kernel(const int* __restrict__ labels) {
    extern __shared__ __align__(128) char smraw[];
    const uint32_t smb = smem_u32(smraw);
    int*   labI   = reinterpret_cast<int*>(smraw + SM_LABI);
    int*   labJ   = reinterpret_cast<int*>(smraw + SM_LABJ);
    float* smRowZ = reinterpret_cast<float*>(smraw + SM_ROWZ);
    float* smRowW = reinterpret_cast<float*>(smraw + SM_ROWW);
    float* smColZ = reinterpret_cast<float*>(smraw + SM_COLZ);
    float* smColW = reinterpret_cast<float*>(smraw + SM_COLW);

    const int tid = threadIdx.x;
    const int wid = tid >> 5;
    const int lane = tid & 31;
    const int warpM = wid & 3;
    const int warpN = wid >> 2;
    const int iBase = blockIdx.y * BM;
    const int jBase = blockIdx.x * BN;

    // init stats + labels (256 rows, 128 cols)
    smRowZ[tid] = 0.f; smRowW[tid] = 0.f;
    labI[tid] = get_label(labels, iBase + tid);
    if (tid < BN) {
        smColZ[tid] = 0.f; smColW[tid] = 0.f;
        labJ[tid] = get_label(labels, jBase + tid);
    }

    const uint8_t* __restrict__ gA = g_imgQ;
    const uint8_t* __restrict__ gB = g_txtQ;

    // per-thread load coords: A 4 passes (256 rows), B 2 passes (128 rows)
    const int rA = tid >> 2, cA = tid & 3;
    const uint32_t soA = sw_off(rA, cA);          // pass p adds row 64 -> +4096 bytes (swizzle-invariant)
    const uint8_t* pA = gA + (size_t)(iBase + rA) * DD + cA * 16;
    const uint8_t* pB = gB + (size_t)(jBase + rA) * DD + cA * 16;

#define LOAD_STAGE(s, kc)                                                     \
    do {                                                                      \
        _Pragma("unroll")                                                     \
        for (int p = 0; p < 4; p++)                                           \
            cp_async16(smb + SM_A(s) + soA + p * 4096u,                       \
                       pA + (size_t)p * 64 * DD + (kc));                      \
        _Pragma("unroll")                                                     \
        for (int p = 0; p < 2; p++)                                           \
            cp_async16(smb + SM_B(s) + soA + p * 4096u,                       \
                       pB + (size_t)p * 64 * DD + (kc));                      \
    } while (0)

    // prologue: stages 0,1
    LOAD_STAGE(0, 0);
    CP_COMMIT();
    LOAD_STAGE(1, BK);
    CP_COMMIT();

    uint32_t acc[4][8][2];
#pragma unroll
    for (int mt = 0; mt < 4; mt++)
#pragma unroll
        for (int nt = 0; nt < 8; nt++) { acc[mt][nt][0] = 0u; acc[mt][nt][1] = 0u; }

    __syncthreads();   // covers label/stat init ordering before epilogue use (and nothing reads tiles yet)

#pragma unroll
    for (int it = 0; it < NITER; it++) {
        CP_WAIT(1);
        __syncthreads();

        if (it + 2 < NITER) {
            const int buf = (it + 2) % NSTAGE;
            LOAD_STAGE(buf, (it + 2) * BK);
        }
        CP_COMMIT();

        const int buf = it % NSTAGE;
        const uint32_t aBase = smb + SM_A(buf);
        const uint32_t bBase = smb + SM_B(buf);
#pragma unroll
        for (int ks = 0; ks < 2; ks++) {   // two k=32 steps per 64B chunk
            uint32_t a[4][4], b[4][4];
            const int lrow = lane & 15;
            const int lch = ks * 2 + (lane >> 4);
#pragma unroll
            for (int mt = 0; mt < 4; mt++) {
                int row = warpM * 64 + mt * 16 + lrow;
                ldsm_x4(a[mt], aBase + sw_off(row, lch));
            }
#pragma unroll
            for (int n2 = 0; n2 < 4; n2++) {
                int row = warpN * 64 + n2 * 16 + lrow;
                ldsm_x4(b[n2], bBase + sw_off(row, lch));
            }
#pragma unroll
            for (int mt = 0; mt < 4; mt++)
#pragma unroll
                for (int nt = 0; nt < 8; nt++)
                    mma_fp8_h(acc[mt][nt], a[mt], b[nt >> 1][nt & 1], b[nt >> 1][(nt & 1) + 2]);
        }
    }
    __syncthreads();

    // ---- fused epilogue ----
    const int g = lane >> 2;
    const int tc = (lane & 3) * 2;

    float rowZ[4][2], rowW[4][2], colZ[8][2];
#pragma unroll
    for (int mt = 0; mt < 4; mt++) { rowZ[mt][0] = rowZ[mt][1] = rowW[mt][0] = rowW[mt][1] = 0.f; }
#pragma unroll
    for (int nt = 0; nt < 8; nt++) { colZ[nt][0] = colZ[nt][1] = 0.f; }

#pragma unroll
    for (int mt = 0; mt < 4; mt++) {
#pragma unroll
        for (int i = 0; i < 2; i++) {
            const int r = warpM * 64 + mt * 16 + g + i * 8;
            const int gi = iBase + r;
            const int li = labI[r];
#pragma unroll
            for (int nt = 0; nt < 8; nt++) {
                float2 p = __half22float2(*reinterpret_cast<const __half2*>(&acc[mt][nt][i]));
#pragma unroll
                for (int c = 0; c < 2; c++) {
                    const int col = warpN * 64 + nt * 8 + tc + c;
                    float s = SC * (c ? p.y : p.x);
                    float e = __expf(s);
                    rowZ[mt][i] += e;
                    colZ[nt][c] += e;
                    bool msk = (gi == jBase + col) || ((li == labJ[col]) && (li != -1));
                    if (msk) { rowW[mt][i] += s; atomicAdd(&smColW[col], s); }
                }
            }
        }
    }

#pragma unroll
    for (int mt = 0; mt < 4; mt++)
#pragma unroll
        for (int i = 0; i < 2; i++) {
#pragma unroll
            for (int m = 1; m <= 2; m <<= 1) {
                rowZ[mt][i] += __shfl_xor_sync(0xffffffffu, rowZ[mt][i], m);
                rowW[mt][i] += __shfl_xor_sync(0xffffffffu, rowW[mt][i], m);
            }
            if ((lane & 3) == 0) {
                int r = warpM * 64 + mt * 16 + g + i * 8;
                atomicAdd(&smRowZ[r], rowZ[mt][i]);
                atomicAdd(&smRowW[r], rowW[mt][i]);
            }
        }
#pragma unroll
    for (int nt = 0; nt < 8; nt++)
#pragma unroll
        for (int c = 0; c < 2; c++) {
#pragma unroll
            for (int m = 4; m <= 16; m <<= 1)
                colZ[nt][c] += __shfl_xor_sync(0xffffffffu, colZ[nt][c], m);
            if (lane < 4) atomicAdd(&smColZ[warpN * 64 + nt * 8 + tc + c], colZ[nt][c]);
        }
    __syncthreads();

    atomicAdd(&g_stats[iBase + tid],          smRowZ[tid]);
    atomicAdd(&g_stats[2 * NN + iBase + tid], smRowW[tid]);
    if (tid < BN) {
        atomicAdd(&g_stats[NN + jBase + tid],     smColZ[tid]);
        atomicAdd(&g_stats[3 * NN + jBase + tid], smColW[tid]);
    }
}

// ---------------- final reduction -> scalar loss (parallel) ----------------
__global__ void reduce_kernel(const int* __restrict__ labels, float* __restrict__ out) {
    __shared__ float red[8];
    const int t = threadIdx.x;
    const int i = blockIdx.x * 256 + t;
    int l = get_label(labels, i);
    float invC = (l >= 0) ? (1.0f / (float)g_cnt[l]) : 1.0f;
    float acc = __logf(g_stats[i])      - g_stats[2 * NN + i] * invC
              + __logf(g_stats[NN + i]) - g_stats[3 * NN + i] * invC;
#pragma unroll
    for (int m = 16; m; m >>= 1) acc += __shfl_xor_sync(0xffffffffu, acc, m);
    if ((t & 31) == 0) red[t >> 5] = acc;
    __syncthreads();
    if (t < 32) {
        float v = (t < 8) ? red[t] : 0.f;
#pragma unroll
        for (int m = 4; m; m >>= 1) v += __shfl_xor_sync(0xffffffffu, v, m);
        if (t == 0) atomicAdd(out, v / (2.0f * NN));
    }
}

extern "C" void kernel_launch(void* const* d_in, const int* in_sizes, int n_in,
                              void* d_out, int out_size) {
    const float* txt = (const float*)d_in[0];
    const float* img = (const float*)d_in[1];
    const int* labels = (const int*)d_in[2];

    cudaFuncSetAttribute(gemm_mma_kernel, cudaFuncAttributeMaxDynamicSharedMemorySize, SM_TOTAL);

    detect_labels_kernel<<<1, 1024>>>(labels, (float*)d_out);
    prep_kernel<<<dim3(NN, 2), 128>>>(txt, img);
    hist_kernel<<<NN / 256, 256>>>(labels);                                 // idx 2
    gemm_mma_kernel<<<dim3(NN / BN, NN / BM), 256, SM_TOTAL>>>(labels);     // idx 3 -> ncu
    reduce_kernel<<<NN / 256, 256>>>(labels, (float*)d_out);
}

// round 11
// speedup vs baseline: 1.1262x; 1.1262x over previous
#include <cuda_runtime.h>
#include <cuda_fp16.h>
#include <stdint.h>

#define NN 8192
#define DD 512
#define LOGIT_SCALE 2.659f
#define FSCALE 32.0f
#define SC (LOGIT_SCALE / (FSCALE * FSCALE))
#define BM 128
#define BN 128
#define BK 64                              // fp8 elems per k-chunk (64 B/row)
#define NITER (DD / BK)                    // 8
#define NSTAGE 3
#define NTHR 512

// dynamic SMEM layout (bytes)
#define SM_A(s)   ((s) * 8192)             // 3 x 8KB (128 rows x 64B)
#define SM_B(s)   (24576 + (s) * 8192)     // 3 x 8KB
#define SM_LABI   49152                    // 128 ints
#define SM_LABJ   49664
#define SM_ROWZ   50176                    // 128 f
#define SM_ROWW   50688
#define SM_COLZ   51200
#define SM_COLW   51712
#define SM_TOTAL  52224

// ---- scratch (__device__ globals; no allocations allowed) ----
__device__ uint8_t g_imgQ[NN * DD];        // e4m3, normalized features x FSCALE
__device__ uint8_t g_txtQ[NN * DD];
__device__ float g_stats[4 * NN];          // [Zimg | Ztxt | Wimg | Wtxt]
__device__ int   g_cnt[100];
__device__ int   g_lab64;

// =============== helpers ===============
__device__ __forceinline__ uint32_t smem_u32(const void* p) {
    uint32_t a;
    asm("{ .reg .u64 t; cvta.to.shared.u64 t, %1; cvt.u32.u64 %0, t; }" : "=r"(a) : "l"(p));
    return a;
}
__device__ __forceinline__ void cp_async16(uint32_t s, const void* g) {
    uint64_t gg;
    asm("cvta.to.global.u64 %0, %1;" : "=l"(gg) : "l"(g));
    asm volatile("cp.async.cg.shared.global [%0], [%1], 16;" :: "r"(s), "l"(gg) : "memory");
}
#define CP_COMMIT() asm volatile("cp.async.commit_group;" ::: "memory")
#define CP_WAIT(n)  asm volatile("cp.async.wait_group %0;" :: "n"(n) : "memory")

__device__ __forceinline__ void ldsm_x4(uint32_t* r, uint32_t addr) {
    asm volatile("ldmatrix.sync.aligned.m8n8.x4.shared.b16 {%0,%1,%2,%3}, [%4];"
                 : "=r"(r[0]), "=r"(r[1]), "=r"(r[2]), "=r"(r[3]) : "r"(addr));
}
// fp8 e4m3 MMA, m16n8k32, fp16 accumulate
__device__ __forceinline__ void mma_fp8_h(uint32_t* d, const uint32_t* a, uint32_t b0, uint32_t b1) {
    asm volatile("mma.sync.aligned.m16n8k32.row.col.f16.e4m3.e4m3.f16 "
                 "{%0,%1}, {%2,%3,%4,%5}, {%6,%7}, {%0,%1};"
                 : "+r"(d[0]), "+r"(d[1])
                 : "r"(a[0]), "r"(a[1]), "r"(a[2]), "r"(a[3]), "r"(b0), "r"(b1));
}
__device__ __forceinline__ uint16_t pack_e4m3x2(float lo, float hi) {
    uint16_t r;
    asm("cvt.rn.satfinite.e4m3x2.f32 %0, %2, %1;" : "=h"(r) : "f"(lo), "f"(hi));
    return r;
}

// swizzled byte offset inside a [rows x 64B] stage (4 x 16B chunks per row)
__device__ __forceinline__ uint32_t sw_off(int row, int ch) {
    return (uint32_t)(row * 4 + (ch ^ ((row >> 1) & 3))) * 16u;
}

__device__ __forceinline__ int get_label(const int* __restrict__ labels, int i) {
    return g_lab64 ? labels[2 * i] : labels[i];
}

// ---------------- detect labels dtype + zero g_cnt + zero out ----------------
__global__ void detect_labels_kernel(const int* __restrict__ labels, float* __restrict__ out) {
    __shared__ int bad;
    const int t = threadIdx.x;
    if (t == 0) { bad = 0; out[0] = 0.0f; }
    if (t < 100) g_cnt[t] = 0;
    __syncthreads();
    int mybad = 0;
    for (int i = t; i < NN / 2; i += blockDim.x) {
        int lo = labels[2 * i];
        int hi = labels[2 * i + 1];
        if (hi != (lo < 0 ? -1 : 0)) mybad = 1;
    }
    if (mybad) bad = 1;
    __syncthreads();
    if (t == 0) g_lab64 = (bad == 0) ? 1 : 0;
}

// ---------------- normalize + fp32 -> e4m3(xFSCALE) + zero stats ----------------
__global__ void prep_kernel(const float* __restrict__ txt, const float* __restrict__ img) {
    const int row = blockIdx.x;
    const int t = threadIdx.x;
    const float* __restrict__ src = blockIdx.y ? txt : img;
    uint8_t* __restrict__ dst = blockIdx.y ? g_txtQ : g_imgQ;

    if (blockIdx.y == 0 && t < 4) g_stats[row * 4 + t] = 0.0f;

    float4 v = reinterpret_cast<const float4*>(src)[row * (DD / 4) + t];
    float ss = v.x * v.x + v.y * v.y + v.z * v.z + v.w * v.w;
#pragma unroll
    for (int m = 16; m; m >>= 1) ss += __shfl_xor_sync(0xffffffffu, ss, m);
    __shared__ float sm[4];
    if ((t & 31) == 0) sm[t >> 5] = ss;
    __syncthreads();
    float tot = sm[0] + sm[1] + sm[2] + sm[3];
    float inv = FSCALE / fmaxf(sqrtf(tot), 1e-12f);
    uint16_t lo = pack_e4m3x2(v.x * inv, v.y * inv);
    uint16_t hi = pack_e4m3x2(v.z * inv, v.w * inv);
    reinterpret_cast<uint32_t*>(dst)[row * (DD / 4) + t] = (uint32_t)lo | ((uint32_t)hi << 16);
}

// ---------------- label histogram (parallel; independent of gemm) ----------------
__global__ void hist_kernel(const int* __restrict__ labels) {
    int i = blockIdx.x * blockDim.x + threadIdx.x;
    if (i < NN) {
        int l = get_label(labels, i);
        if (l >= 0) atomicAdd(&g_cnt[l], 1);
    }
}

// ---------------- FP8 QMMA GEMM (512 thr, warp tile 32x32) + fused statistics ----------------
// grid (64, 64), 512 threads (16 warps = 4M x 4N).
__global__ __launch_bounds__(NTHR, 2) void gemm_mma_kernel(const int* __restrict__ labels) {
    extern __shared__ __align__(128) char smraw[];
    const uint32_t smb = smem_u32(smraw);
    int*   labI   = reinterpret_cast<int*>(smraw + SM_LABI);
    int*   labJ   = reinterpret_cast<int*>(smraw + SM_LABJ);
    float* smRowZ = reinterpret_cast<float*>(smraw + SM_ROWZ);
    float* smRowW = reinterpret_cast<float*>(smraw + SM_ROWW);
    float* smColZ = reinterpret_cast<float*>(smraw + SM_COLZ);
    float* smColW = reinterpret_cast<float*>(smraw + SM_COLW);

    const int tid = threadIdx.x;
    const int wid = tid >> 5;
    const int lane = tid & 31;
    const int warpM = wid & 3;
    const int warpN = wid >> 2;
    const int iBase = blockIdx.y * BM;
    const int jBase = blockIdx.x * BN;

    if (tid < BM) {
        smRowZ[tid] = 0.f; smRowW[tid] = 0.f;
        smColZ[tid] = 0.f; smColW[tid] = 0.f;
        labI[tid] = get_label(labels, iBase + tid);
        labJ[tid] = get_label(labels, jBase + tid);
    }

    const uint8_t* __restrict__ gA = g_imgQ;
    const uint8_t* __restrict__ gB = g_txtQ;

    // per-thread load coords: 512 slots == 128 rows x 4 chunks, one A + one B cp each
    const int rA = tid >> 2, cA = tid & 3;
    const uint32_t soA = sw_off(rA, cA);
    const uint8_t* pA = gA + (size_t)(iBase + rA) * DD + cA * 16;
    const uint8_t* pB = gB + (size_t)(jBase + rA) * DD + cA * 16;

#define LOAD_STAGE(s, kc)                                \
    do {                                                 \
        cp_async16(smb + SM_A(s) + soA, pA + (kc));      \
        cp_async16(smb + SM_B(s) + soA, pB + (kc));      \
    } while (0)

    // prologue: stages 0,1
    LOAD_STAGE(0, 0);
    CP_COMMIT();
    LOAD_STAGE(1, BK);
    CP_COMMIT();

    uint32_t acc[2][4][2];                 // f16x2: [mt][nt][row-half]
#pragma unroll
    for (int mt = 0; mt < 2; mt++)
#pragma unroll
        for (int nt = 0; nt < 4; nt++) { acc[mt][nt][0] = 0u; acc[mt][nt][1] = 0u; }

    __syncthreads();

#pragma unroll
    for (int it = 0; it < NITER; it++) {
        CP_WAIT(1);
        __syncthreads();

        if (it + 2 < NITER) {
            const int buf = (it + 2) % NSTAGE;
            LOAD_STAGE(buf, (it + 2) * BK);
        }
        CP_COMMIT();

        const int buf = it % NSTAGE;
        const uint32_t aBase = smb + SM_A(buf);
        const uint32_t bBase = smb + SM_B(buf);
#pragma unroll
        for (int ks = 0; ks < 2; ks++) {   // two k=32 steps per 64B chunk
            uint32_t a[2][4], b[2][4];
            const int lrow = lane & 15;
            const int lch = ks * 2 + (lane >> 4);
#pragma unroll
            for (int mt = 0; mt < 2; mt++)
                ldsm_x4(a[mt], aBase + sw_off(warpM * 32 + mt * 16 + lrow, lch));
#pragma unroll
            for (int n2 = 0; n2 < 2; n2++)
                ldsm_x4(b[n2], bBase + sw_off(warpN * 32 + n2 * 16 + lrow, lch));
#pragma unroll
            for (int mt = 0; mt < 2; mt++)
#pragma unroll
                for (int nt = 0; nt < 4; nt++)
                    mma_fp8_h(acc[mt][nt], a[mt], b[nt >> 1][nt & 1], b[nt >> 1][(nt & 1) + 2]);
        }
    }
    __syncthreads();

    // ---- fused epilogue ----
    const int g = lane >> 2;
    const int tc = (lane & 3) * 2;

    float rowZ[2][2], rowW[2][2], colZ[4][2];
#pragma unroll
    for (int mt = 0; mt < 2; mt++) { rowZ[mt][0] = rowZ[mt][1] = rowW[mt][0] = rowW[mt][1] = 0.f; }
#pragma unroll
    for (int nt = 0; nt < 4; nt++) { colZ[nt][0] = colZ[nt][1] = 0.f; }

#pragma unroll
    for (int mt = 0; mt < 2; mt++) {
#pragma unroll
        for (int i = 0; i < 2; i++) {
            const int r = warpM * 32 + mt * 16 + g + i * 8;
            const int gi = iBase + r;
            const int li = labI[r];
#pragma unroll
            for (int nt = 0; nt < 4; nt++) {
                float2 p = __half22float2(*reinterpret_cast<const __half2*>(&acc[mt][nt][i]));
#pragma unroll
                for (int c = 0; c < 2; c++) {
                    const int col = warpN * 32 + nt * 8 + tc + c;
                    float s = SC * (c ? p.y : p.x);
                    float e = __expf(s);
                    rowZ[mt][i] += e;
                    colZ[nt][c] += e;
                    bool msk = (gi == jBase + col) || ((li == labJ[col]) && (li != -1));
                    if (msk) { rowW[mt][i] += s; atomicAdd(&smColW[col], s); }
                }
            }
        }
    }

#pragma unroll
    for (int mt = 0; mt < 2; mt++)
#pragma unroll
        for (int i = 0; i < 2; i++) {
#pragma unroll
            for (int m = 1; m <= 2; m <<= 1) {
                rowZ[mt][i] += __shfl_xor_sync(0xffffffffu, rowZ[mt][i], m);
                rowW[mt][i] += __shfl_xor_sync(0xffffffffu, rowW[mt][i], m);
            }
            if ((lane & 3) == 0) {
                int r = warpM * 32 + mt * 16 + g + i * 8;
                atomicAdd(&smRowZ[r], rowZ[mt][i]);
                atomicAdd(&smRowW[r], rowW[mt][i]);
            }
        }
#pragma unroll
    for (int nt = 0; nt < 4; nt++)
#pragma unroll
        for (int c = 0; c < 2; c++) {
#pragma unroll
            for (int m = 4; m <= 16; m <<= 1)
                colZ[nt][c] += __shfl_xor_sync(0xffffffffu, colZ[nt][c], m);
            if (lane < 4) atomicAdd(&smColZ[warpN * 32 + nt * 8 + tc + c], colZ[nt][c]);
        }
    __syncthreads();

    if (tid < BM) {
        atomicAdd(&g_stats[iBase + tid],          smRowZ[tid]);
        atomicAdd(&g_stats[2 * NN + iBase + tid], smRowW[tid]);
        atomicAdd(&g_stats[NN + jBase + tid],     smColZ[tid]);
        atomicAdd(&g_stats[3 * NN + jBase + tid], smColW[tid]);
    }
}

// ---------------- final reduction -> scalar loss (parallel) ----------------
__global__ void reduce_kernel(const int* __restrict__ labels, float* __restrict__ out) {
    __shared__ float red[8];
    const int t = threadIdx.x;
    const int i = blockIdx.x * 256 + t;
    int l = get_label(labels, i);
    float invC = (l >= 0) ? (1.0f / (float)g_cnt[l]) : 1.0f;
    float acc = __logf(g_stats[i])      - g_stats[2 * NN + i] * invC
              + __logf(g_stats[NN + i]) - g_stats[3 * NN + i] * invC;
#pragma unroll
    for (int m = 16; m; m >>= 1) acc += __shfl_xor_sync(0xffffffffu, acc, m);
    if ((t & 31) == 0) red[t >> 5] = acc;
    __syncthreads();
    if (t < 32) {
        float v = (t < 8) ? red[t] : 0.f;
#pragma unroll
        for (int m = 4; m; m >>= 1) v += __shfl_xor_sync(0xffffffffu, v, m);
        if (t == 0) atomicAdd(out, v / (2.0f * NN));
    }
}

extern "C" void kernel_launch(void* const* d_in, const int* in_sizes, int n_in,
                              void* d_out, int out_size) {
    const float* txt = (const float*)d_in[0];
    const float* img = (const float*)d_in[1];
    const int* labels = (const int*)d_in[2];

    cudaFuncSetAttribute(gemm_mma_kernel, cudaFuncAttributeMaxDynamicSharedMemorySize, SM_TOTAL);

    detect_labels_kernel<<<1, 1024>>>(labels, (float*)d_out);
    prep_kernel<<<dim3(NN, 2), 128>>>(txt, img);
    hist_kernel<<<NN / 256, 256>>>(labels);                                  // idx 2
    gemm_mma_kernel<<<dim3(NN / BN, NN / BM), NTHR, SM_TOTAL>>>(labels);     // idx 3 -> ncu
    reduce_kernel<<<NN / 256, 256>>>(labels, (float*)d_out);
}

// round 13
// speedup vs baseline: 1.1333x; 1.0063x over previous
#include <cuda_runtime.h>
#include <cuda_fp16.h>
#include <stdint.h>

#define NN 8192
#define DD 512
#define LOGIT_SCALE 2.659f
#define FSCALE 32.0f
#define SC (LOGIT_SCALE / (FSCALE * FSCALE))
#define BM 128
#define BN 128
#define BK 64                              // fp8 elems per k-chunk (64 B/row)
#define NITER (DD / BK)                    // 8
#define NSTAGE 3
#define NTHR 512

// dynamic SMEM layout (bytes)
#define SM_A(s)   ((s) * 8192)             // 3 x 8KB (128 rows x 64B)
#define SM_B(s)   (24576 + (s) * 8192)     // 3 x 8KB
#define SM_LABI   49152                    // 128 ints
#define SM_LABJ   49664
#define SM_ROWZ   50176                    // 128 f
#define SM_ROWW   50688
#define SM_COLZ   51200
#define SM_COLW   51712
#define SM_TOTAL  52224

// ---- scratch (__device__ globals; no allocations allowed) ----
__device__ uint8_t g_imgQ[NN * DD];        // e4m3, normalized features x FSCALE
__device__ uint8_t g_txtQ[NN * DD];
__device__ float g_stats[4 * NN];          // [Zimg | Ztxt | Wimg | Wtxt]
__device__ int   g_cnt[100];
__device__ int   g_lab64;

// =============== helpers ===============
__device__ __forceinline__ uint32_t smem_u32(const void* p) {
    uint32_t a;
    asm("{ .reg .u64 t; cvta.to.shared.u64 t, %1; cvt.u32.u64 %0, t; }" : "=r"(a) : "l"(p));
    return a;
}
__device__ __forceinline__ void cp_async16(uint32_t s, const void* g) {
    uint64_t gg;
    asm("cvta.to.global.u64 %0, %1;" : "=l"(gg) : "l"(g));
    asm volatile("cp.async.cg.shared.global [%0], [%1], 16;" :: "r"(s), "l"(gg) : "memory");
}
#define CP_COMMIT() asm volatile("cp.async.commit_group;" ::: "memory")
#define CP_WAIT(n)  asm volatile("cp.async.wait_group %0;" :: "n"(n) : "memory")

__device__ __forceinline__ void ldsm_x4(uint32_t* r, uint32_t addr) {
    asm volatile("ldmatrix.sync.aligned.m8n8.x4.shared.b16 {%0,%1,%2,%3}, [%4];"
                 : "=r"(r[0]), "=r"(r[1]), "=r"(r[2]), "=r"(r[3]) : "r"(addr));
}
// fp8 e4m3 MMA, m16n8k32, fp16 accumulate
__device__ __forceinline__ void mma_fp8_h(uint32_t* d, const uint32_t* a, uint32_t b0, uint32_t b1) {
    asm volatile("mma.sync.aligned.m16n8k32.row.col.f16.e4m3.e4m3.f16 "
                 "{%0,%1}, {%2,%3,%4,%5}, {%6,%7}, {%0,%1};"
                 : "+r"(d[0]), "+r"(d[1])
                 : "r"(a[0]), "r"(a[1]), "r"(a[2]), "r"(a[3]), "r"(b0), "r"(b1));
}
__device__ __forceinline__ uint16_t pack_e4m3x2(float lo, float hi) {
    uint16_t r;
    asm("cvt.rn.satfinite.e4m3x2.f32 %0, %2, %1;" : "=h"(r) : "f"(lo), "f"(hi));
    return r;
}

// swizzled byte offset inside a [rows x 64B] stage (4 x 16B chunks per row)
__device__ __forceinline__ uint32_t sw_off(int row, int ch) {
    return (uint32_t)(row * 4 + (ch ^ ((row >> 1) & 3))) * 16u;
}

__device__ __forceinline__ int get_label(const int* __restrict__ labels, int i) {
    return g_lab64 ? labels[2 * i] : labels[i];
}

// ---------------- detect labels dtype + zero g_cnt + zero out ----------------
__global__ void detect_labels_kernel(const int* __restrict__ labels, float* __restrict__ out) {
    __shared__ int bad;
    const int t = threadIdx.x;
    if (t == 0) { bad = 0; out[0] = 0.0f; }
    if (t < 100) g_cnt[t] = 0;
    __syncthreads();
    int mybad = 0;
    for (int i = t; i < NN / 2; i += blockDim.x) {
        int lo = labels[2 * i];
        int hi = labels[2 * i + 1];
        if (hi != (lo < 0 ? -1 : 0)) mybad = 1;
    }
    if (mybad) bad = 1;
    __syncthreads();
    if (t == 0) g_lab64 = (bad == 0) ? 1 : 0;
}

// ---------------- normalize + fp32 -> e4m3(xFSCALE) + zero stats ----------------
__global__ void prep_kernel(const float* __restrict__ txt, const float* __restrict__ img) {
    const int row = blockIdx.x;
    const int t = threadIdx.x;
    const float* __restrict__ src = blockIdx.y ? txt : img;
    uint8_t* __restrict__ dst = blockIdx.y ? g_txtQ : g_imgQ;

    if (blockIdx.y == 0 && t < 4) g_stats[row * 4 + t] = 0.0f;

    float4 v = reinterpret_cast<const float4*>(src)[row * (DD / 4) + t];
    float ss = v.x * v.x + v.y * v.y + v.z * v.z + v.w * v.w;
#pragma unroll
    for (int m = 16; m; m >>= 1) ss += __shfl_xor_sync(0xffffffffu, ss, m);
    __shared__ float sm[4];
    if ((t & 31) == 0) sm[t >> 5] = ss;
    __syncthreads();
    float tot = sm[0] + sm[1] + sm[2] + sm[3];
    float inv = FSCALE / fmaxf(sqrtf(tot), 1e-12f);
    uint16_t lo = pack_e4m3x2(v.x * inv, v.y * inv);
    uint16_t hi = pack_e4m3x2(v.z * inv, v.w * inv);
    reinterpret_cast<uint32_t*>(dst)[row * (DD / 4) + t] = (uint32_t)lo | ((uint32_t)hi << 16);
}

// ---------------- label histogram (parallel; independent of gemm) ----------------
__global__ void hist_kernel(const int* __restrict__ labels) {
    int i = blockIdx.x * blockDim.x + threadIdx.x;
    if (i < NN) {
        int l = get_label(labels, i);
        if (l >= 0) atomicAdd(&g_cnt[l], 1);
    }
}

// ---------------- FP8 QMMA GEMM (512 thr, warp tile 32x32) + fused statistics ----------------
// grid (64, 64), 512 threads (16 warps = 4M x 4N).
__global__ __launch_bounds__(NTHR, 2) void gemm_mma_kernel(const int* __restrict__ labels) {
    extern __shared__ __align__(128) char smraw[];
    const uint32_t smb = smem_u32(smraw);
    int*   labI   = reinterpret_cast<int*>(smraw + SM_LABI);
    int*   labJ   = reinterpret_cast<int*>(smraw + SM_LABJ);
    float* smRowZ = reinterpret_cast<float*>(smraw + SM_ROWZ);
    float* smRowW = reinterpret_cast<float*>(smraw + SM_ROWW);
    float* smColZ = reinterpret_cast<float*>(smraw + SM_COLZ);
    float* smColW = reinterpret_cast<float*>(smraw + SM_COLW);

    const int tid = threadIdx.x;
    const int wid = tid >> 5;
    const int lane = tid & 31;
    const int warpM = wid & 3;
    const int warpN = wid >> 2;
    const int iBase = blockIdx.y * BM;
    const int jBase = blockIdx.x * BN;

    if (tid < BM) {
        smRowZ[tid] = 0.f; smRowW[tid] = 0.f;
        smColZ[tid] = 0.f; smColW[tid] = 0.f;
        labI[tid] = get_label(labels, iBase + tid);
        labJ[tid] = get_label(labels, jBase + tid);
    }

    const uint8_t* __restrict__ gA = g_imgQ;
    const uint8_t* __restrict__ gB = g_txtQ;

    // per-thread load coords: 512 slots == 128 rows x 4 chunks, one A + one B cp each
    const int rA = tid >> 2, cA = tid & 3;
    const uint32_t soA = sw_off(rA, cA);
    const uint8_t* pA = gA + (size_t)(iBase + rA) * DD + cA * 16;
    const uint8_t* pB = gB + (size_t)(jBase + rA) * DD + cA * 16;

#define LOAD_STAGE(s, kc)                                \
    do {                                                 \
        cp_async16(smb + SM_A(s) + soA, pA + (kc));      \
        cp_async16(smb + SM_B(s) + soA, pB + (kc));      \
    } while (0)

    // ---- HOISTED ldsm offsets: loop-invariant per thread (8 registers) ----
    const int lrow = lane & 15;
    const int lgrp = lane >> 4;
    uint32_t offA[2][2], offB[2][2];
#pragma unroll
    for (int ks = 0; ks < 2; ks++) {
        const int lch = ks * 2 + lgrp;
#pragma unroll
        for (int f = 0; f < 2; f++) {
            offA[ks][f] = sw_off(warpM * 32 + f * 16 + lrow, lch);
            offB[ks][f] = sw_off(warpN * 32 + f * 16 + lrow, lch);
        }
    }

    // prologue: stages 0,1
    LOAD_STAGE(0, 0);
    CP_COMMIT();
    LOAD_STAGE(1, BK);
    CP_COMMIT();

    uint32_t acc[2][4][2];                 // f16x2: [mt][nt][row-half]
#pragma unroll
    for (int mt = 0; mt < 2; mt++)
#pragma unroll
        for (int nt = 0; nt < 4; nt++) { acc[mt][nt][0] = 0u; acc[mt][nt][1] = 0u; }

    __syncthreads();

#pragma unroll
    for (int it = 0; it < NITER; it++) {
        CP_WAIT(1);
        __syncthreads();

        if (it + 2 < NITER) {
            const int buf = (it + 2) % NSTAGE;
            LOAD_STAGE(buf, (it + 2) * BK);
        }
        CP_COMMIT();

        const int buf = it % NSTAGE;
        const uint32_t aBase = smb + SM_A(buf);
        const uint32_t bBase = smb + SM_B(buf);
#pragma unroll
        for (int ks = 0; ks < 2; ks++) {   // two k=32 steps per 64B chunk
            uint32_t a[2][4], b[2][4];
            ldsm_x4(a[0], aBase + offA[ks][0]);
            ldsm_x4(a[1], aBase + offA[ks][1]);
            ldsm_x4(b[0], bBase + offB[ks][0]);
            ldsm_x4(b[1], bBase + offB[ks][1]);
#pragma unroll
            for (int mt = 0; mt < 2; mt++)
#pragma unroll
                for (int nt = 0; nt < 4; nt++)
                    mma_fp8_h(acc[mt][nt], a[mt], b[nt >> 1][nt & 1], b[nt >> 1][(nt & 1) + 2]);
        }
    }
    __syncthreads();

    // ---- fused epilogue ----
    const int g = lane >> 2;
    const int tc = (lane & 3) * 2;

    float rowZ[2][2], rowW[2][2], colZ[4][2];
#pragma unroll
    for (int mt = 0; mt < 2; mt++) { rowZ[mt][0] = rowZ[mt][1] = rowW[mt][0] = rowW[mt][1] = 0.f; }
#pragma unroll
    for (int nt = 0; nt < 4; nt++) { colZ[nt][0] = colZ[nt][1] = 0.f; }

#pragma unroll
    for (int mt = 0; mt < 2; mt++) {
#pragma unroll
        for (int i = 0; i < 2; i++) {
            const int r = warpM * 32 + mt * 16 + g + i * 8;
            const int gi = iBase + r;
            const int li = labI[r];
#pragma unroll
            for (int nt = 0; nt < 4; nt++) {
                float2 p = __half22float2(*reinterpret_cast<const __half2*>(&acc[mt][nt][i]));
#pragma unroll
                for (int c = 0; c < 2; c++) {
                    const int col = warpN * 32 + nt * 8 + tc + c;
                    float s = SC * (c ? p.y : p.x);
                    float e = __expf(s);
                    rowZ[mt][i] += e;
                    colZ[nt][c] += e;
                    bool msk = (gi == jBase + col) || ((li == labJ[col]) && (li != -1));
                    if (msk) { rowW[mt][i] += s; atomicAdd(&smColW[col], s); }
                }
            }
        }
    }

#pragma unroll
    for (int mt = 0; mt < 2; mt++)
#pragma unroll
        for (int i = 0; i < 2; i++) {
#pragma unroll
            for (int m = 1; m <= 2; m <<= 1) {
                rowZ[mt][i] += __shfl_xor_sync(0xffffffffu, rowZ[mt][i], m);
                rowW[mt][i] += __shfl_xor_sync(0xffffffffu, rowW[mt][i], m);
            }
            if ((lane & 3) == 0) {
                int r = warpM * 32 + mt * 16 + g + i * 8;
                atomicAdd(&smRowZ[r], rowZ[mt][i]);
                atomicAdd(&smRowW[r], rowW[mt][i]);
            }
        }
#pragma unroll
    for (int nt = 0; nt < 4; nt++)
#pragma unroll
        for (int c = 0; c < 2; c++) {
#pragma unroll
            for (int m = 4; m <= 16; m <<= 1)
                colZ[nt][c] += __shfl_xor_sync(0xffffffffu, colZ[nt][c], m);
            if (lane < 4) atomicAdd(&smColZ[warpN * 32 + nt * 8 + tc + c], colZ[nt][c]);
        }
    __syncthreads();

    if (tid < BM) {
        atomicAdd(&g_stats[iBase + tid],          smRowZ[tid]);
        atomicAdd(&g_stats[2 * NN + iBase + tid], smRowW[tid]);
        atomicAdd(&g_stats[NN + jBase + tid],     smColZ[tid]);
        atomicAdd(&g_stats[3 * NN + jBase + tid], smColW[tid]);
    }
}

// ---------------- final reduction -> scalar loss (parallel) ----------------
__global__ void reduce_kernel(const int* __restrict__ labels, float* __restrict__ out) {
    __shared__ float red[8];
    const int t = threadIdx.x;
    const int i = blockIdx.x * 256 + t;
    int l = get_label(labels, i);
    float invC = (l >= 0) ? (1.0f / (float)g_cnt[l]) : 1.0f;
    float acc = __logf(g_stats[i])      - g_stats[2 * NN + i] * invC
              + __logf(g_stats[NN + i]) - g_stats[3 * NN + i] * invC;
#pragma unroll
    for (int m = 16; m; m >>= 1) acc += __shfl_xor_sync(0xffffffffu, acc, m);
    if ((t & 31) == 0) red[t >> 5] = acc;
    __syncthreads();
    if (t < 32) {
        float v = (t < 8) ? red[t] : 0.f;
#pragma unroll
        for (int m = 4; m; m >>= 1) v += __shfl_xor_sync(0xffffffffu, v, m);
        if (t == 0) atomicAdd(out, v / (2.0f * NN));
    }
}

extern "C" void kernel_launch(void* const* d_in, const int* in_sizes, int n_in,
                              void* d_out, int out_size) {
    const float* txt = (const float*)d_in[0];
    const float* img = (const float*)d_in[1];
    const int* labels = (const int*)d_in[2];

    cudaFuncSetAttribute(gemm_mma_kernel, cudaFuncAttributeMaxDynamicSharedMemorySize, SM_TOTAL);

    detect_labels_kernel<<<1, 1024>>>(labels, (float*)d_out);
    prep_kernel<<<dim3(NN, 2), 128>>>(txt, img);
    hist_kernel<<<NN / 256, 256>>>(labels);                                  // idx 2
    gemm_mma_kernel<<<dim3(NN / BN, NN / BM), NTHR, SM_TOTAL>>>(labels);     // idx 3 -> ncu
    reduce_kernel<<<NN / 256, 256>>>(labels, (float*)d_out);
}